// round 6
// baseline (speedup 1.0000x reference)
#include <cuda_runtime.h>
#include <cuda_bf16.h>
#include <cstdint>

#define M_DIM 4096
#define N_DIM 8192
#define K_DIM 2048
#define K2    4096            // [hi | lo] along K

// GEMM tiling
#define BM 128
#define BN 128
#define BK 32
#define NSTAGE 3
#define KT_TILES (K_DIM / BK)   // 64
#define NTHREADS 512

// smem: padded rows, 32 bf16 data + 8 pad = 40 bf16 = 80 bytes per row
#define ROW_B     80
#define TILE_B    (BM * ROW_B)          // 10240 per operand tile
#define AHI_OFF   0
#define ALO_OFF   10240
#define BHI_OFF   20480
#define BLO_OFF   30720
#define STAGE_B   40960
#define SMEM_TOTAL (NSTAGE * STAGE_B)   // 122880

// ---------------------------------------------------------------------------
// device scratch (allocation-free)
// ---------------------------------------------------------------------------
__device__ __nv_bfloat16 g_A2[(size_t)M_DIM * K2];   // [M, 2K]: hi | lo
__device__ __nv_bfloat16 g_B2[(size_t)N_DIM * K2];   // [N, 2K]: hi | lo
__device__ float g_scratch[(size_t)M_DIM * N_DIM];
__device__ unsigned g_rowmax_u[M_DIM];

// ---------------------------------------------------------------------------
// helpers
// ---------------------------------------------------------------------------
__device__ __forceinline__ uint32_t smem_u32(const void* p) {
    uint32_t a;
    asm("{ .reg .u64 t; cvta.to.shared.u64 t, %1; cvt.u32.u64 %0, t; }" : "=r"(a) : "l"(p));
    return a;
}

#define CP_ASYNC16(smem_addr, gptr) \
    asm volatile("cp.async.cg.shared.global [%0], [%1], 16;" :: "r"(smem_addr), "l"(gptr))
#define CP_COMMIT() asm volatile("cp.async.commit_group;" ::: "memory")
#define CP_WAIT1()  asm volatile("cp.async.wait_group 1;" ::: "memory")

__device__ __forceinline__ void ldsm_x4(uint32_t* r, uint32_t addr) {
    asm volatile("ldmatrix.sync.aligned.m8n8.x4.shared.b16 {%0,%1,%2,%3}, [%4];"
                 : "=r"(r[0]), "=r"(r[1]), "=r"(r[2]), "=r"(r[3]) : "r"(addr));
}

__device__ __forceinline__ void mma16816(float* d, const uint32_t* a, const uint32_t* b) {
    asm volatile(
        "mma.sync.aligned.m16n8k16.row.col.f32.bf16.bf16.f32 "
        "{%0,%1,%2,%3}, {%4,%5,%6,%7}, {%8,%9}, {%0,%1,%2,%3};"
        : "+f"(d[0]), "+f"(d[1]), "+f"(d[2]), "+f"(d[3])
        : "r"(a[0]), "r"(a[1]), "r"(a[2]), "r"(a[3]), "r"(b[0]), "r"(b[1]));
}

// order-preserving float<->uint for atomicMax-based rowmax
__device__ __forceinline__ unsigned f2ord(float x) {
    unsigned u = __float_as_uint(x);
    return (u & 0x80000000u) ? ~u : (u | 0x80000000u);
}
__device__ __forceinline__ float ord2f(unsigned u) {
    u = (u & 0x80000000u) ? (u ^ 0x80000000u) : ~u;
    return __uint_as_float(u);
}

// ---------------------------------------------------------------------------
// split fp32 -> bf16 [hi | lo] along K (dst row stride K2)
// ---------------------------------------------------------------------------
__global__ __launch_bounds__(256)
void split_kernel(const float* __restrict__ src, __nv_bfloat16* __restrict__ dst) {
    size_t i = (size_t)blockIdx.x * 256 + threadIdx.x;      // float4 index
    float4 v = reinterpret_cast<const float4*>(src)[i];
    size_t r = i >> 9;          // / (2048/4)
    size_t k4 = (i & 511) * 4;
    float f[4] = {v.x, v.y, v.z, v.w};
    __nv_bfloat16 h[4], l[4];
#pragma unroll
    for (int j = 0; j < 4; j++) {
        h[j] = __float2bfloat16(f[j]);
        l[j] = __float2bfloat16(f[j] - __bfloat162float(h[j]));
    }
    __nv_bfloat162* dh = reinterpret_cast<__nv_bfloat162*>(dst + r * K2 + k4);
    __nv_bfloat162* dl = reinterpret_cast<__nv_bfloat162*>(dst + r * K2 + K_DIM + k4);
    dh[0] = __nv_bfloat162{h[0], h[1]};
    dh[1] = __nv_bfloat162{h[2], h[3]};
    dl[0] = __nv_bfloat162{l[0], l[1]};
    dl[1] = __nv_bfloat162{l[2], l[3]};
}

__global__ __launch_bounds__(256)
void init_rowmax_kernel(unsigned* __restrict__ rmax) {
    int i = blockIdx.x * 256 + threadIdx.x;
    if (i < M_DIM) rmax[i] = 0u;   // ordered-uint 0 == "below -inf"
}

// ---------------------------------------------------------------------------
// bf16 split-GEMM via mma.sync, 512 threads, term-outermost mma ordering
// C[M,N] = Ahi*Bhi^T + Alo*Bhi^T + Ahi*Blo^T
// ---------------------------------------------------------------------------
__global__ __launch_bounds__(NTHREADS, 1)
void hgemm_kernel(const __nv_bfloat16* __restrict__ A,
                  const __nv_bfloat16* __restrict__ B,
                  float* __restrict__ C,
                  unsigned* __restrict__ rmax) {
    extern __shared__ __align__(128) char smem[];
    const uint32_t sb = smem_u32(smem);
    const int tid = threadIdx.x;
    const int wid = tid >> 5;
    const int lid = tid & 31;
    const int warp_m = wid & 3;      // 4 warps along M (32 rows each)
    const int warp_n = wid >> 2;     // 4 warps along N (32 cols each)

    // grouped raster: 32 m-tiles x 64 n-tiles, GROUP_M = 8
    const int num_n = N_DIM / BN;                 // 64
    const int pid = blockIdx.x;
    const int grp = pid / (8 * num_n);
    const int pm = grp * 8 + (pid & 7);
    const int pn = (pid % (8 * num_n)) >> 3;
    const int bm = pm * BM;
    const int bn = pn * BN;

    // gmem load mapping: 512 threads cover 128 rows x 4 chunks(16B) per tile
    const int r0 = tid >> 2;         // 0..127
    const int cc = tid & 3;          // 16B chunk within 32-col (64B) row
    const __nv_bfloat16* gA = A + (size_t)(bm + r0) * K2 + cc * 8;
    const __nv_bfloat16* gB = B + (size_t)(bn + r0) * K2 + cc * 8;
    const uint32_t s_off = (uint32_t)r0 * ROW_B + cc * 16;

    auto load_stage = [&](int s, int kt) {
        uint32_t st = sb + s * STAGE_B;
        const int kc = kt * BK;
        const __nv_bfloat16* a = gA + kc;
        const __nv_bfloat16* b = gB + kc;
        CP_ASYNC16(st + AHI_OFF + s_off, a);
        CP_ASYNC16(st + ALO_OFF + s_off, a + K_DIM);
        CP_ASYNC16(st + BHI_OFF + s_off, b);
        CP_ASYNC16(st + BLO_OFF + s_off, b + K_DIM);
    };

    float acc[2][4][4];
#pragma unroll
    for (int i = 0; i < 2; i++)
#pragma unroll
        for (int j = 0; j < 4; j++)
#pragma unroll
            for (int q = 0; q < 4; q++)
                acc[i][j][q] = 0.0f;

    load_stage(0, 0); CP_COMMIT();
    load_stage(1, 1); CP_COMMIT();

    // ldmatrix lane addressing
    const int a_row = warp_m * 32 + (lid & 15);                         // + i*16
    const int a_kh  = (lid >> 4) * 16;
    const int b_row = warp_n * 32 + (lid & 7) + ((lid >> 4) & 1) * 8;   // + j*16
    const int b_kh  = ((lid >> 3) & 1) * 16;

    for (int kt = 0; kt < KT_TILES; kt++) {
        const int s = kt % NSTAGE;
        CP_WAIT1();
        __syncthreads();
        if (kt + 2 < KT_TILES) load_stage((kt + 2) % NSTAGE, kt + 2);
        CP_COMMIT();

        const uint32_t st = sb + s * STAGE_B;
#pragma unroll
        for (int ks = 0; ks < 2; ks++) {
            uint32_t ah[2][4], al[2][4], bh[8], bl[8];
#pragma unroll
            for (int i = 0; i < 2; i++) {
                uint32_t rb = (uint32_t)(a_row + i * 16) * ROW_B + ks * 32 + a_kh;
                ldsm_x4(ah[i], st + AHI_OFF + rb);
                ldsm_x4(al[i], st + ALO_OFF + rb);
            }
#pragma unroll
            for (int j = 0; j < 2; j++) {
                uint32_t rb = (uint32_t)(b_row + j * 16) * ROW_B + ks * 32 + b_kh;
                ldsm_x4(bh + j * 4, st + BHI_OFF + rb);
                ldsm_x4(bl + j * 4, st + BLO_OFF + rb);
            }
            // term-outermost: same-accumulator reuse distance = 8 mmas
#pragma unroll
            for (int i = 0; i < 2; i++)
#pragma unroll
                for (int jj = 0; jj < 4; jj++)
                    mma16816(acc[i][jj], ah[i], bh + jj * 2);   // hi*hi
#pragma unroll
            for (int i = 0; i < 2; i++)
#pragma unroll
                for (int jj = 0; jj < 4; jj++)
                    mma16816(acc[i][jj], al[i], bh + jj * 2);   // lo*hi
#pragma unroll
            for (int i = 0; i < 2; i++)
#pragma unroll
                for (int jj = 0; jj < 4; jj++)
                    mma16816(acc[i][jj], ah[i], bl + jj * 2);   // hi*lo
        }
    }

    // epilogue: store C + fused row-max atomics
    const int erow = bm + warp_m * 32 + (lid >> 2);
    const int ecol = bn + warp_n * 32 + (lid & 3) * 2;
#pragma unroll
    for (int i = 0; i < 2; i++) {
#pragma unroll
        for (int half = 0; half < 2; half++) {
            float m = -3.402823466e+38f;
#pragma unroll
            for (int jj = 0; jj < 4; jj++) {
                float v0 = acc[i][jj][half * 2 + 0];
                float v1 = acc[i][jj][half * 2 + 1];
                float* p = C + (size_t)(erow + i * 16 + half * 8) * N_DIM + ecol + jj * 8;
                *reinterpret_cast<float2*>(p) = make_float2(v0, v1);
                m = fmaxf(m, fmaxf(v0, v1));
            }
            m = fmaxf(m, __shfl_xor_sync(0xffffffffu, m, 1));
            m = fmaxf(m, __shfl_xor_sync(0xffffffffu, m, 2));
            if ((lid & 3) == 0)
                atomicMax(&rmax[erow + i * 16 + half * 8], f2ord(m));
        }
    }
}

// ---------------------------------------------------------------------------
// gelu epilogue
// ---------------------------------------------------------------------------
__device__ __forceinline__ float gelu_tanh(float x) {
    const float c0 = 0.7978845608028654f;
    const float c1 = 0.044715f;
    float inner = c0 * fmaf(c1 * x, x * x, x);
    return 0.5f * x * (1.0f + tanhf(inner));
}

__global__ __launch_bounds__(256)
void gelu_kernel(const float* __restrict__ C, const unsigned* __restrict__ rmax,
                 float* __restrict__ out) {
    const size_t base = (size_t)blockIdx.x * 4096;
    const int row = (int)(base / N_DIM);
    const float mx = ord2f(rmax[row]);
    const float4* c4 = reinterpret_cast<const float4*>(C + base);
    float4* o4 = reinterpret_cast<float4*>(out + base);
    const int tid = threadIdx.x;
#pragma unroll
    for (int it = 0; it < 4; it++) {
        float4 v = c4[tid + it * 256];
        float4 r;
        r.x = gelu_tanh(v.x - mx);
        r.y = gelu_tanh(v.y - mx);
        r.z = gelu_tanh(v.z - mx);
        r.w = gelu_tanh(v.w - mx);
        o4[tid + it * 256] = r;
    }
}

// ---------------------------------------------------------------------------
extern "C" void kernel_launch(void* const* d_in, const int* in_sizes, int n_in,
                              void* d_out, int out_size) {
    const float* x = (const float*)d_in[0];   // [M, K]
    const float* w = (const float*)d_in[1];   // [N, K]
    float* out = (float*)d_out;               // [M, N]

    void *a2, *b2, *scratch, *rowmax;
    cudaGetSymbolAddress(&a2, g_A2);
    cudaGetSymbolAddress(&b2, g_B2);
    cudaGetSymbolAddress(&scratch, g_scratch);
    cudaGetSymbolAddress(&rowmax, g_rowmax_u);

    split_kernel<<<(M_DIM * (K_DIM / 4)) / 256, 256>>>(x, (__nv_bfloat16*)a2);
    split_kernel<<<(N_DIM * (K_DIM / 4)) / 256, 256>>>(w, (__nv_bfloat16*)b2);
    init_rowmax_kernel<<<M_DIM / 256, 256>>>((unsigned*)rowmax);

    cudaFuncSetAttribute(hgemm_kernel, cudaFuncAttributeMaxDynamicSharedMemorySize, SMEM_TOTAL);
    hgemm_kernel<<<(M_DIM / BM) * (N_DIM / BN), NTHREADS, SMEM_TOTAL>>>(
        (const __nv_bfloat16*)a2, (const __nv_bfloat16*)b2,
        (float*)scratch, (unsigned*)rowmax);

    gelu_kernel<<<(size_t)M_DIM * N_DIM / 4096, 256>>>(
        (float*)scratch, (unsigned*)rowmax, out);
}

// round 7
// speedup vs baseline: 1.0560x; 1.0560x over previous
#include <cuda_runtime.h>
#include <cuda_bf16.h>
#include <cstdint>

#define M_DIM 4096
#define N_DIM 8192
#define K_DIM 2048
#define K2    4096            // [hi | lo] along K

// GEMM tiling
#define BM 128
#define BN 128
#define BK 64
#define NSTAGE 3
#define KT_TILES (K_DIM / BK)   // 32
#define NTHREADS 512

// smem: padded rows, 64 bf16 data + 8 pad = 72 bf16 = 144 bytes per row
#define ROW_B     144
#define TILE_B    (BM * ROW_B)          // 18432 per operand tile
#define AHI_OFF   0
#define ALO_OFF   18432
#define BHI_OFF   36864
#define BLO_OFF   55296
#define STAGE_B   73728
#define SMEM_TOTAL (NSTAGE * STAGE_B)   // 221184

// ---------------------------------------------------------------------------
// device scratch (allocation-free)
// ---------------------------------------------------------------------------
__device__ __nv_bfloat16 g_A2[(size_t)M_DIM * K2];   // [M, 2K]: hi | lo
__device__ __nv_bfloat16 g_B2[(size_t)N_DIM * K2];   // [N, 2K]: hi | lo
__device__ float g_scratch[(size_t)M_DIM * N_DIM];
__device__ unsigned g_rowmax_u[M_DIM];

// ---------------------------------------------------------------------------
// helpers
// ---------------------------------------------------------------------------
__device__ __forceinline__ uint32_t smem_u32(const void* p) {
    uint32_t a;
    asm("{ .reg .u64 t; cvta.to.shared.u64 t, %1; cvt.u32.u64 %0, t; }" : "=r"(a) : "l"(p));
    return a;
}

#define CP_ASYNC16(smem_addr, gptr) \
    asm volatile("cp.async.cg.shared.global [%0], [%1], 16;" :: "r"(smem_addr), "l"(gptr))
#define CP_COMMIT() asm volatile("cp.async.commit_group;" ::: "memory")
#define CP_WAIT1()  asm volatile("cp.async.wait_group 1;" ::: "memory")

__device__ __forceinline__ void ldsm_x4(uint32_t* r, uint32_t addr) {
    asm volatile("ldmatrix.sync.aligned.m8n8.x4.shared.b16 {%0,%1,%2,%3}, [%4];"
                 : "=r"(r[0]), "=r"(r[1]), "=r"(r[2]), "=r"(r[3]) : "r"(addr));
}

__device__ __forceinline__ void mma16816(float* d, const uint32_t* a, const uint32_t* b) {
    asm volatile(
        "mma.sync.aligned.m16n8k16.row.col.f32.bf16.bf16.f32 "
        "{%0,%1,%2,%3}, {%4,%5,%6,%7}, {%8,%9}, {%0,%1,%2,%3};"
        : "+f"(d[0]), "+f"(d[1]), "+f"(d[2]), "+f"(d[3])
        : "r"(a[0]), "r"(a[1]), "r"(a[2]), "r"(a[3]), "r"(b[0]), "r"(b[1]));
}

// order-preserving float<->uint for atomicMax-based rowmax
__device__ __forceinline__ unsigned f2ord(float x) {
    unsigned u = __float_as_uint(x);
    return (u & 0x80000000u) ? ~u : (u | 0x80000000u);
}
__device__ __forceinline__ float ord2f(unsigned u) {
    u = (u & 0x80000000u) ? (u ^ 0x80000000u) : ~u;
    return __uint_as_float(u);
}

// ---------------------------------------------------------------------------
// split fp32 -> bf16 [hi | lo] along K (dst row stride K2)
// ---------------------------------------------------------------------------
__global__ __launch_bounds__(256)
void split_kernel(const float* __restrict__ src, __nv_bfloat16* __restrict__ dst) {
    size_t i = (size_t)blockIdx.x * 256 + threadIdx.x;      // float4 index
    float4 v = reinterpret_cast<const float4*>(src)[i];
    size_t r = i >> 9;          // / (2048/4)
    size_t k4 = (i & 511) * 4;
    float f[4] = {v.x, v.y, v.z, v.w};
    __nv_bfloat16 h[4], l[4];
#pragma unroll
    for (int j = 0; j < 4; j++) {
        h[j] = __float2bfloat16(f[j]);
        l[j] = __float2bfloat16(f[j] - __bfloat162float(h[j]));
    }
    __nv_bfloat162* dh = reinterpret_cast<__nv_bfloat162*>(dst + r * K2 + k4);
    __nv_bfloat162* dl = reinterpret_cast<__nv_bfloat162*>(dst + r * K2 + K_DIM + k4);
    dh[0] = __nv_bfloat162{h[0], h[1]};
    dh[1] = __nv_bfloat162{h[2], h[3]};
    dl[0] = __nv_bfloat162{l[0], l[1]};
    dl[1] = __nv_bfloat162{l[2], l[3]};
}

__global__ __launch_bounds__(256)
void init_rowmax_kernel(unsigned* __restrict__ rmax) {
    int i = blockIdx.x * 256 + threadIdx.x;
    if (i < M_DIM) rmax[i] = 0u;   // ordered-uint 0 == "below -inf"
}

// ---------------------------------------------------------------------------
// bf16 split-GEMM via mma.sync: BK=64, double-buffered fragments, fused rowmax
// C[M,N] = Ahi*Bhi^T + Alo*Bhi^T + Ahi*Blo^T
// ---------------------------------------------------------------------------
__global__ __launch_bounds__(NTHREADS, 1)
void hgemm_kernel(const __nv_bfloat16* __restrict__ A,
                  const __nv_bfloat16* __restrict__ B,
                  float* __restrict__ C,
                  unsigned* __restrict__ rmax) {
    extern __shared__ __align__(128) char smem[];
    const uint32_t sb = smem_u32(smem);
    const int tid = threadIdx.x;
    const int wid = tid >> 5;
    const int lid = tid & 31;
    const int warp_m = wid & 3;      // 4 warps along M (32 rows each)
    const int warp_n = wid >> 2;     // 4 warps along N (32 cols each)

    // grouped raster: 32 m-tiles x 64 n-tiles, GROUP_M = 8
    const int num_n = N_DIM / BN;                 // 64
    const int pid = blockIdx.x;
    const int grp = pid / (8 * num_n);
    const int pm = grp * 8 + (pid & 7);
    const int pn = (pid % (8 * num_n)) >> 3;
    const int bm = pm * BM;
    const int bn = pn * BN;

    // gmem load mapping: 512 threads; 4 threads cover one 128B row (8 chunks)
    const int r0 = tid >> 2;          // 0..127
    const int cc = (tid & 3) * 2;     // chunk pair: cc, cc+1 (each 16B)
    const __nv_bfloat16* gA = A + (size_t)(bm + r0) * K2 + cc * 8;
    const __nv_bfloat16* gB = B + (size_t)(bn + r0) * K2 + cc * 8;
    const uint32_t s_off = (uint32_t)r0 * ROW_B + cc * 16;

    auto load_stage = [&](int s, int kt) {
        uint32_t st = sb + s * STAGE_B;
        const int kc = kt * BK;
        const __nv_bfloat16* a = gA + kc;
        const __nv_bfloat16* b = gB + kc;
        CP_ASYNC16(st + AHI_OFF + s_off,      a);
        CP_ASYNC16(st + AHI_OFF + s_off + 16, a + 8);
        CP_ASYNC16(st + ALO_OFF + s_off,      a + K_DIM);
        CP_ASYNC16(st + ALO_OFF + s_off + 16, a + K_DIM + 8);
        CP_ASYNC16(st + BHI_OFF + s_off,      b);
        CP_ASYNC16(st + BHI_OFF + s_off + 16, b + 8);
        CP_ASYNC16(st + BLO_OFF + s_off,      b + K_DIM);
        CP_ASYNC16(st + BLO_OFF + s_off + 16, b + K_DIM + 8);
    };

    float acc[2][4][4];
#pragma unroll
    for (int i = 0; i < 2; i++)
#pragma unroll
        for (int j = 0; j < 4; j++)
#pragma unroll
            for (int q = 0; q < 4; q++)
                acc[i][j][q] = 0.0f;

    load_stage(0, 0); CP_COMMIT();
    load_stage(1, 1); CP_COMMIT();

    // ldmatrix lane addressing
    const int a_row = warp_m * 32 + (lid & 15);                         // + i*16
    const int a_kh  = (lid >> 4) * 16;
    const int b_row = warp_n * 32 + (lid & 7) + ((lid >> 4) & 1) * 8;   // + j*16
    const int b_kh  = ((lid >> 3) & 1) * 16;

    // double-buffered fragments
    uint32_t ah[2][2][4], al[2][2][4], bh[2][8], bl[2][8];

    for (int kt = 0; kt < KT_TILES; kt++) {
        const int s = kt % NSTAGE;
        CP_WAIT1();
        __syncthreads();
        if (kt + 2 < KT_TILES) load_stage((kt + 2) % NSTAGE, kt + 2);
        CP_COMMIT();

        const uint32_t st = sb + s * STAGE_B;

        // prime buffer 0 with ks=0 fragments
#pragma unroll
        for (int i = 0; i < 2; i++) {
            uint32_t rb = (uint32_t)(a_row + i * 16) * ROW_B + a_kh;
            ldsm_x4(ah[0][i], st + AHI_OFF + rb);
            ldsm_x4(al[0][i], st + ALO_OFF + rb);
        }
#pragma unroll
        for (int j = 0; j < 2; j++) {
            uint32_t rb = (uint32_t)(b_row + j * 16) * ROW_B + b_kh;
            ldsm_x4(bh[0] + j * 4, st + BHI_OFF + rb);
            ldsm_x4(bl[0] + j * 4, st + BLO_OFF + rb);
        }

#pragma unroll
        for (int ks = 0; ks < 4; ks++) {
            const int cur = ks & 1;
            const int nxt = cur ^ 1;
            if (ks < 3) {
                const uint32_t ko = (uint32_t)(ks + 1) * 32;
#pragma unroll
                for (int i = 0; i < 2; i++) {
                    uint32_t rb = (uint32_t)(a_row + i * 16) * ROW_B + ko + a_kh;
                    ldsm_x4(ah[nxt][i], st + AHI_OFF + rb);
                    ldsm_x4(al[nxt][i], st + ALO_OFF + rb);
                }
#pragma unroll
                for (int j = 0; j < 2; j++) {
                    uint32_t rb = (uint32_t)(b_row + j * 16) * ROW_B + ko + b_kh;
                    ldsm_x4(bh[nxt] + j * 4, st + BHI_OFF + rb);
                    ldsm_x4(bl[nxt] + j * 4, st + BLO_OFF + rb);
                }
            }
#pragma unroll
            for (int i = 0; i < 2; i++)
#pragma unroll
                for (int jj = 0; jj < 4; jj++) {
                    mma16816(acc[i][jj], ah[cur][i], bh[cur] + jj * 2);   // hi*hi
                    mma16816(acc[i][jj], al[cur][i], bh[cur] + jj * 2);   // lo*hi
                    mma16816(acc[i][jj], ah[cur][i], bl[cur] + jj * 2);   // hi*lo
                }
        }
    }

    // epilogue: store C + fused row-max atomics
    const int erow = bm + warp_m * 32 + (lid >> 2);
    const int ecol = bn + warp_n * 32 + (lid & 3) * 2;
#pragma unroll
    for (int i = 0; i < 2; i++) {
#pragma unroll
        for (int half = 0; half < 2; half++) {
            float m = -3.402823466e+38f;
#pragma unroll
            for (int jj = 0; jj < 4; jj++) {
                float v0 = acc[i][jj][half * 2 + 0];
                float v1 = acc[i][jj][half * 2 + 1];
                float* p = C + (size_t)(erow + i * 16 + half * 8) * N_DIM + ecol + jj * 8;
                *reinterpret_cast<float2*>(p) = make_float2(v0, v1);
                m = fmaxf(m, fmaxf(v0, v1));
            }
            m = fmaxf(m, __shfl_xor_sync(0xffffffffu, m, 1));
            m = fmaxf(m, __shfl_xor_sync(0xffffffffu, m, 2));
            if ((lid & 3) == 0)
                atomicMax(&rmax[erow + i * 16 + half * 8], f2ord(m));
        }
    }
}

// ---------------------------------------------------------------------------
// gelu epilogue
// ---------------------------------------------------------------------------
__device__ __forceinline__ float gelu_tanh(float x) {
    const float c0 = 0.7978845608028654f;
    const float c1 = 0.044715f;
    float inner = c0 * fmaf(c1 * x, x * x, x);
    return 0.5f * x * (1.0f + tanhf(inner));
}

__global__ __launch_bounds__(256)
void gelu_kernel(const float* __restrict__ C, const unsigned* __restrict__ rmax,
                 float* __restrict__ out) {
    const size_t base = (size_t)blockIdx.x * 4096;
    const int row = (int)(base / N_DIM);
    const float mx = ord2f(rmax[row]);
    const float4* c4 = reinterpret_cast<const float4*>(C + base);
    float4* o4 = reinterpret_cast<float4*>(out + base);
    const int tid = threadIdx.x;
#pragma unroll
    for (int it = 0; it < 4; it++) {
        float4 v = c4[tid + it * 256];
        float4 r;
        r.x = gelu_tanh(v.x - mx);
        r.y = gelu_tanh(v.y - mx);
        r.z = gelu_tanh(v.z - mx);
        r.w = gelu_tanh(v.w - mx);
        o4[tid + it * 256] = r;
    }
}

// ---------------------------------------------------------------------------
extern "C" void kernel_launch(void* const* d_in, const int* in_sizes, int n_in,
                              void* d_out, int out_size) {
    const float* x = (const float*)d_in[0];   // [M, K]
    const float* w = (const float*)d_in[1];   // [N, K]
    float* out = (float*)d_out;               // [M, N]

    void *a2, *b2, *scratch, *rowmax;
    cudaGetSymbolAddress(&a2, g_A2);
    cudaGetSymbolAddress(&b2, g_B2);
    cudaGetSymbolAddress(&scratch, g_scratch);
    cudaGetSymbolAddress(&rowmax, g_rowmax_u);

    split_kernel<<<(M_DIM * (K_DIM / 4)) / 256, 256>>>(x, (__nv_bfloat16*)a2);
    split_kernel<<<(N_DIM * (K_DIM / 4)) / 256, 256>>>(w, (__nv_bfloat16*)b2);
    init_rowmax_kernel<<<M_DIM / 256, 256>>>((unsigned*)rowmax);

    cudaFuncSetAttribute(hgemm_kernel, cudaFuncAttributeMaxDynamicSharedMemorySize, SMEM_TOTAL);
    hgemm_kernel<<<(M_DIM / BM) * (N_DIM / BN), NTHREADS, SMEM_TOTAL>>>(
        (const __nv_bfloat16*)a2, (const __nv_bfloat16*)b2,
        (float*)scratch, (unsigned*)rowmax);

    gelu_kernel<<<(size_t)M_DIM * N_DIM / 4096, 256>>>(
        (float*)scratch, (unsigned*)rowmax, out);
}